// round 16
// baseline (speedup 1.0000x reference)
#include <cuda_runtime.h>
#include <cuda_bf16.h>
#include <cstdint>

// ---------------- problem constants ----------------
#define NN     100000
#define EE     1600000
#define ET     1700000          // EE + NN self loops
#define DIM    128
#define ODIM   64
#define GDIM   512              // 4*DIM
#define KLSTM  384              // h_tmp(128) | x(128) | h(128)
#define NEG_SLOPE 0.2f
#define RESW   0.5f
#define SCANB  1024
#define NBLK   ((NN + SCANB - 1) / SCANB)   // 98

// ---------------- device scratch ----------------
__device__ float g_x0[NN * DIM];
__device__ float g_x [NN * DIM];
__device__ float g_xp[NN * 3 * DIM];        // [n][l*128+d] fp32
__device__ float g_c [NN * DIM];
__device__ float g_gates[NN * GDIM];
__device__ float g_as[3 * NN];
__device__ float g_ad[3 * NN];
__device__ int   g_cnt[NN];
__device__ int   g_cur[NN];
__device__ int   g_off[NN + 1];
__device__ int   g_bsum[128];
__device__ int   g_srcl[ET];                // CSR: src ids grouped by dst
__device__ float g_Wfused[512 * DIM];       // rows 0-127: lin1_w; rows 128-511: W1ᵀ·Wg
__device__ float g_biasF[512];
__device__ __nv_bfloat16 g_Wlsb[3 * GDIM * KLSTM];  // gate weights bf16, n-major
__device__ __nv_bfloat16 g_xpb[NN * 3 * DIM];       // bf16 copy of xp for agg gather
__device__ __nv_bfloat16 g_x0b[NN * DIM];
__device__ __nv_bfloat16 g_xb [NN * DIM];
__device__ __nv_bfloat16 g_hb [NN * DIM];
__device__ __nv_bfloat16 g_htb[NN * DIM];

__device__ __forceinline__ float sigf(float x) { return 1.f / (1.f + __expf(-x)); }

__device__ __forceinline__ void st_bf4(__nv_bfloat16* p, float4 v) {
    __nv_bfloat162* q = (__nv_bfloat162*)p;
    q[0] = __floats2bfloat162_rn(v.x, v.y);
    q[1] = __floats2bfloat162_rn(v.z, v.w);
}

// ---------------- weight prep ----------------
__global__ void k_prep(const float* __restrict__ l1w, const float* __restrict__ l1b,
                       const float* __restrict__ wih, const float* __restrict__ whh) {
    const int W1_TOT = DIM * DIM;
    const int TOT = W1_TOT + 512 + 3 * GDIM * KLSTM;
    for (int i = blockIdx.x * blockDim.x + threadIdx.x; i < TOT; i += gridDim.x * blockDim.x) {
        if (i < W1_TOT) {
            g_Wfused[i] = l1w[i];
        } else if (i < W1_TOT + 512) {
            int n = i - W1_TOT;
            if (n < 128) g_biasF[n] = l1b[n];
        } else {
            int t = i - W1_TOT - 512;
            int l = t / (GDIM * KLSTM);
            int r = t % (GDIM * KLSTM);
            int j = r / KLSTM, k = r % KLSTM;
            float v = (k < 256) ? wih[l * GDIM * 256 + j * 256 + k]
                                : whh[l * GDIM * 128 + j * 128 + (k - 256)];
            g_Wlsb[t] = __float2bfloat16_rn(v);
        }
    }
}

// compose Wc[n][k] = sum_j lin1_w[j][k] * gat_W[l][j][d]; bc[n] = sum_j b1[j]*Wg
__global__ void k_compose(const float* __restrict__ l1w, const float* __restrict__ l1b,
                          const float* __restrict__ gatw) {
    int t = blockIdx.x * blockDim.x + threadIdx.x;
    const int NCMP = 384 * 128;
    if (t < NCMP) {
        int n = t >> 7, k = t & 127;
        int l = n >> 7, d = n & 127;
        const float* wg = gatw + l * 16384 + d;
        float s = 0.f;
#pragma unroll 8
        for (int j = 0; j < 128; j++)
            s += l1w[j * 128 + k] * wg[j * 128];
        g_Wfused[(128 + n) * 128 + k] = s;
    } else if (t < NCMP + 384) {
        int n = t - NCMP;
        int l = n >> 7, d = n & 127;
        const float* wg = gatw + l * 16384 + d;
        float s = 0.f;
#pragma unroll 8
        for (int j = 0; j < 128; j++)
            s += l1b[j] * wg[j * 128];
        g_biasF[128 + n] = s;
    }
}

// ---------------- CSR build (one-time) ----------------
__global__ void k_zero_cnt() {
    for (int i = blockIdx.x * blockDim.x + threadIdx.x; i < NN; i += gridDim.x * blockDim.x) {
        g_cnt[i] = 0; g_cur[i] = 0;
    }
}

__global__ void k_hist(const int* __restrict__ eidx) {
    int e = blockIdx.x * blockDim.x + threadIdx.x;
    if (e >= ET) return;
    int d = (e < EE) ? eidx[EE + e] : e - EE;
    atomicAdd(&g_cnt[d], 1);
}

__global__ void k_scan1() {
    __shared__ int wsum[32];
    int tid = threadIdx.x, lane = tid & 31, wid = tid >> 5;
    int i = blockIdx.x * SCANB + tid;
    int x = (i < NN) ? g_cnt[i] : 0;
#pragma unroll
    for (int off = 1; off < 32; off <<= 1) {
        int t = __shfl_up_sync(0xffffffffu, x, off);
        if (lane >= off) x += t;
    }
    if (lane == 31) wsum[wid] = x;
    __syncthreads();
    if (wid == 0) {
        int y = wsum[lane];
#pragma unroll
        for (int off = 1; off < 32; off <<= 1) {
            int t = __shfl_up_sync(0xffffffffu, y, off);
            if (lane >= off) y += t;
        }
        wsum[lane] = y;
    }
    __syncthreads();
    int incl = x + (wid > 0 ? wsum[wid - 1] : 0);
    if (i < NN) g_off[i + 1] = incl;
    if (tid == SCANB - 1) g_bsum[blockIdx.x] = incl;
}

__global__ void k_scan2() {
    int lane = threadIdx.x;
    int v[4]; int loc = 0;
#pragma unroll
    for (int j = 0; j < 4; j++) {
        int idx = lane * 4 + j;
        v[j] = (idx < NBLK) ? g_bsum[idx] : 0;
        loc += v[j];
    }
    int x = loc;
#pragma unroll
    for (int off = 1; off < 32; off <<= 1) {
        int t = __shfl_up_sync(0xffffffffu, x, off);
        if (lane >= off) x += t;
    }
    int pre = x - loc;
#pragma unroll
    for (int j = 0; j < 4; j++) {
        int idx = lane * 4 + j;
        if (idx < NBLK) g_bsum[idx] = pre;
        pre += v[j];
    }
}

__global__ void k_scan3() {
    int i = blockIdx.x * SCANB + threadIdx.x;
    if (i == 0) g_off[0] = 0;
    if (i < NN) g_off[i + 1] += g_bsum[blockIdx.x];
}

__global__ void k_scatter(const int* __restrict__ eidx) {
    int e = blockIdx.x * blockDim.x + threadIdx.x;
    if (e >= ET) return;
    int s, d;
    if (e < EE) { s = eidx[e]; d = eidx[EE + e]; }
    else        { s = d = e - EE; }
    int pos = g_off[d] + atomicAdd(&g_cur[d], 1);
    g_srcl[pos] = s;
}

// ---------------- common async helpers ----------------
__device__ __forceinline__ void cp16(uint32_t dst, const void* src, int sz) {
    asm volatile("cp.async.cg.shared.global [%0], [%1], 16, %2;\n"
                 :: "r"(dst), "l"(src), "r"(sz));
}

__device__ __forceinline__ void ldm_x4(uint32_t& r0, uint32_t& r1, uint32_t& r2, uint32_t& r3,
                                       uint32_t addr) {
    asm volatile("ldmatrix.sync.aligned.m8n8.x4.shared.b16 {%0,%1,%2,%3}, [%4];"
                 : "=r"(r0), "=r"(r1), "=r"(r2), "=r"(r3) : "r"(addr));
}

// ---------------- tf32 GEMM (projection / lin2), 3-stage, BKT=32 ----------------
#define BKT 32
#define TG_SMEM (6 * 128 * 36 * 4)   // 110592

template <int SPLIT>
__global__ __launch_bounds__(256) void tgemm(
    const float* __restrict__ A0,
    const float* __restrict__ B, const float* __restrict__ bias,
    float* __restrict__ C, float* __restrict__ C2,
    int M, int K, int Nc, int Bld)
{
    extern __shared__ char smem_raw[];
    float (*sA)[128][36] = (float (*)[128][36])smem_raw;
    float (*sB)[128][36] = (float (*)[128][36])(smem_raw + 3 * 128 * 36 * 4);

    const int tid = threadIdx.x;
    const int wid = tid >> 5, lane = tid & 31;
    const int warpM = wid & 1, warpN = wid >> 1;
    const int block_row = blockIdx.y * 128;
    const int block_col = blockIdx.x * 128;
    const int grp = lane >> 2, tig = lane & 3;

    float acc[4][4][4];
#pragma unroll
    for (int mi = 0; mi < 4; mi++)
#pragma unroll
        for (int ni = 0; ni < 4; ni++)
#pragma unroll
            for (int r = 0; r < 4; r++) acc[mi][ni][r] = 0.f;

    const int nKt = K / BKT;

    auto load_stage = [&](int stage, int kt) {
#pragma unroll
        for (int p = 0; p < 4; p++) {
            int i = tid + p * 256;
            int m = i >> 3, kc = i & 7;
            int gr = block_row + m;
            uint32_t dst = (uint32_t)__cvta_generic_to_shared(&sA[stage][m][kc * 4]);
            cp16(dst, A0 + (size_t)gr * K + kt + kc * 4, gr < M ? 16 : 0);
        }
#pragma unroll
        for (int p = 0; p < 4; p++) {
            int i = tid + p * 256;
            int n = i >> 3, kc = i & 7;
            int gn = block_col + n;
            uint32_t dst = (uint32_t)__cvta_generic_to_shared(&sB[stage][n][kc * 4]);
            cp16(dst, B + (size_t)gn * Bld + kt + kc * 4, gn < Nc ? 16 : 0);
        }
        asm volatile("cp.async.commit_group;\n");
    };

    load_stage(0, 0);
    if (nKt > 1) load_stage(1, BKT);
    else         asm volatile("cp.async.commit_group;\n");

    const int aRow = warpM * 64 + (lane & 15);
    const int aKof = (lane >> 4) << 2;
    const int bRow = warpN * 32 + ((lane >> 4) << 3) + (lane & 7);
    const int bKof = ((lane >> 3) & 1) << 2;

    int s = 0;
    for (int it = 0; it < nKt; it++) {
        asm volatile("cp.async.wait_group 1;\n");
        __syncthreads();
        if (it + 2 < nKt) {
            int ns = s + 2; if (ns >= 3) ns -= 3;
            load_stage(ns, (it + 2) * BKT);
        } else {
            asm volatile("cp.async.commit_group;\n");
        }

        const uint32_t aBase = (uint32_t)__cvta_generic_to_shared(&sA[s][0][0]);
        const uint32_t bBase = (uint32_t)__cvta_generic_to_shared(&sB[s][0][0]);
#pragma unroll
        for (int kk = 0; kk < BKT; kk += 8) {
            uint32_t af[4][4];
#pragma unroll
            for (int mi = 0; mi < 4; mi++) {
                uint32_t addr = aBase + (uint32_t)(((aRow + mi * 16) * 36 + kk + aKof) * 4);
                ldm_x4(af[mi][0], af[mi][1], af[mi][2], af[mi][3], addr);
            }
            uint32_t bf[4][2];
#pragma unroll
            for (int nh = 0; nh < 2; nh++) {
                uint32_t addr = bBase + (uint32_t)(((bRow + nh * 16) * 36 + kk + bKof) * 4);
                uint32_t r0, r1, r2, r3;
                ldm_x4(r0, r1, r2, r3, addr);
                bf[nh * 2][0] = r0; bf[nh * 2][1] = r1;
                bf[nh * 2 + 1][0] = r2; bf[nh * 2 + 1][1] = r3;
            }
#pragma unroll
            for (int mi = 0; mi < 4; mi++)
#pragma unroll
                for (int ni = 0; ni < 4; ni++) {
                    asm volatile(
                        "mma.sync.aligned.m16n8k8.row.col.f32.tf32.tf32.f32 "
                        "{%0,%1,%2,%3}, {%4,%5,%6,%7}, {%8,%9}, {%0,%1,%2,%3};"
                        : "+f"(acc[mi][ni][0]), "+f"(acc[mi][ni][1]),
                          "+f"(acc[mi][ni][2]), "+f"(acc[mi][ni][3])
                        : "r"(af[mi][0]), "r"(af[mi][1]), "r"(af[mi][2]), "r"(af[mi][3]),
                          "r"(bf[ni][0]), "r"(bf[ni][1]));
                }
        }
        if (++s >= 3) s -= 3;
    }

    float* Cout; int cstride, cbase;
    if (SPLIT) {
        if (block_col < 128) { Cout = C;  cstride = 128; cbase = block_col; }
        else                 { Cout = C2; cstride = 384; cbase = block_col - 128; }
    } else { Cout = C; cstride = Nc; cbase = block_col; }

#pragma unroll
    for (int mi = 0; mi < 4; mi++) {
#pragma unroll
        for (int ni = 0; ni < 4; ni++) {
            int gr0 = block_row + warpM * 64 + mi * 16 + grp;
            int lc  = warpN * 32 + ni * 8 + 2 * tig;
            int gcol = block_col + lc;
            if (gcol >= Nc) continue;
            float b0 = 0.f, b1 = 0.f;
            if (bias) { b0 = bias[gcol]; b1 = bias[gcol + 1]; }
            int oc = cbase + lc;
            if (gr0 < M) {
                float2 v = make_float2(acc[mi][ni][0] + b0, acc[mi][ni][1] + b1);
                *(float2*)(Cout + (size_t)gr0 * cstride + oc) = v;
            }
            int gr1 = gr0 + 8;
            if (gr1 < M) {
                float2 v = make_float2(acc[mi][ni][2] + b0, acc[mi][ni][3] + b1);
                *(float2*)(Cout + (size_t)gr1 * cstride + oc) = v;
            }
        }
    }
}

// ---------------- bf16 GEMM (gate path), m16n8k16, 3-stage, BKT=32 ----------------
#define TGB_SMEM (6 * 128 * 40 * 2)   // 61440

__global__ __launch_bounds__(256) void tgemm_bf16(
    const __nv_bfloat16* __restrict__ A0, const __nv_bfloat16* __restrict__ A1,
    const __nv_bfloat16* __restrict__ A2,
    const __nv_bfloat16* __restrict__ B, float* __restrict__ C,
    int M, int K, int Nc, int Bld)
{
    extern __shared__ char smem_raw[];
    __nv_bfloat16 (*sA)[128][40] = (__nv_bfloat16 (*)[128][40])smem_raw;
    __nv_bfloat16 (*sB)[128][40] = (__nv_bfloat16 (*)[128][40])(smem_raw + 3 * 128 * 40 * 2);

    const int tid = threadIdx.x;
    const int wid = tid >> 5, lane = tid & 31;
    const int warpM = wid & 1, warpN = wid >> 1;
    const int block_row = blockIdx.y * 128;
    const int block_col = blockIdx.x * 128;
    const int grp = lane >> 2, tig = lane & 3;

    float acc[4][4][4];
#pragma unroll
    for (int mi = 0; mi < 4; mi++)
#pragma unroll
        for (int ni = 0; ni < 4; ni++)
#pragma unroll
            for (int r = 0; r < 4; r++) acc[mi][ni][r] = 0.f;

    const int nKt = K / BKT;

    auto load_stage = [&](int stage, int kt) {
        int seg = kt >> 7;
        const __nv_bfloat16* Ap = (seg == 0) ? A0 : (seg == 1) ? A1 : A2;
        int kb = kt & 127;
#pragma unroll
        for (int p = 0; p < 2; p++) {
            int i = tid + p * 256;
            int m = i >> 2, kc = i & 3;
            int gr = block_row + m;
            uint32_t dst = (uint32_t)__cvta_generic_to_shared(&sA[stage][m][kc * 8]);
            cp16(dst, Ap + (size_t)gr * 128 + kb + kc * 8, gr < M ? 16 : 0);
        }
#pragma unroll
        for (int p = 0; p < 2; p++) {
            int i = tid + p * 256;
            int n = i >> 2, kc = i & 3;
            int gn = block_col + n;
            uint32_t dst = (uint32_t)__cvta_generic_to_shared(&sB[stage][n][kc * 8]);
            cp16(dst, B + (size_t)gn * Bld + kt + kc * 8, gn < Nc ? 16 : 0);
        }
        asm volatile("cp.async.commit_group;\n");
    };

    load_stage(0, 0);
    load_stage(1, BKT);

    const int aRow = warpM * 64 + (lane & 15);
    const int aK8  = (lane >> 4) << 3;
    const int bRow = warpN * 32 + ((lane >> 3) & 1) * 8 + (lane & 7);
    const int bK8  = (lane >> 4) << 3;

    int s = 0;
    for (int it = 0; it < nKt; it++) {
        asm volatile("cp.async.wait_group 1;\n");
        __syncthreads();
        if (it + 2 < nKt) {
            int ns = s + 2; if (ns >= 3) ns -= 3;
            load_stage(ns, (it + 2) * BKT);
        } else {
            asm volatile("cp.async.commit_group;\n");
        }

        const uint32_t aBase = (uint32_t)__cvta_generic_to_shared(&sA[s][0][0]);
        const uint32_t bBase = (uint32_t)__cvta_generic_to_shared(&sB[s][0][0]);
#pragma unroll
        for (int kk = 0; kk < BKT; kk += 16) {
            uint32_t af[4][4];
#pragma unroll
            for (int mi = 0; mi < 4; mi++) {
                uint32_t addr = aBase + (uint32_t)(((aRow + mi * 16) * 40 + kk + aK8) * 2);
                ldm_x4(af[mi][0], af[mi][1], af[mi][2], af[mi][3], addr);
            }
            uint32_t bf[4][2];
#pragma unroll
            for (int nh = 0; nh < 2; nh++) {
                uint32_t addr = bBase + (uint32_t)(((bRow + nh * 16) * 40 + kk + bK8) * 2);
                uint32_t r0, r1, r2, r3;
                ldm_x4(r0, r1, r2, r3, addr);
                bf[nh * 2][0] = r0; bf[nh * 2][1] = r2;
                bf[nh * 2 + 1][0] = r1; bf[nh * 2 + 1][1] = r3;
            }
#pragma unroll
            for (int mi = 0; mi < 4; mi++)
#pragma unroll
                for (int ni = 0; ni < 4; ni++) {
                    asm volatile(
                        "mma.sync.aligned.m16n8k16.row.col.f32.bf16.bf16.f32 "
                        "{%0,%1,%2,%3}, {%4,%5,%6,%7}, {%8,%9}, {%0,%1,%2,%3};"
                        : "+f"(acc[mi][ni][0]), "+f"(acc[mi][ni][1]),
                          "+f"(acc[mi][ni][2]), "+f"(acc[mi][ni][3])
                        : "r"(af[mi][0]), "r"(af[mi][1]), "r"(af[mi][2]), "r"(af[mi][3]),
                          "r"(bf[ni][0]), "r"(bf[ni][1]));
                }
        }
        if (++s >= 3) s -= 3;
    }

#pragma unroll
    for (int mi = 0; mi < 4; mi++) {
#pragma unroll
        for (int ni = 0; ni < 4; ni++) {
            int gr0 = block_row + warpM * 64 + mi * 16 + grp;
            int gc  = block_col + warpN * 32 + ni * 8 + 2 * tig;
            if (gc >= Nc) continue;
            if (gr0 < M) {
                float2 v = make_float2(acc[mi][ni][0], acc[mi][ni][1]);
                *(float2*)(C + (size_t)gr0 * Nc + gc) = v;
            }
            int gr1 = gr0 + 8;
            if (gr1 < M) {
                float2 v = make_float2(acc[mi][ni][2], acc[mi][ni][3]);
                *(float2*)(C + (size_t)gr1 * Nc + gc) = v;
            }
        }
    }
}

// ---------------- attention coefficients + bf16 copies of xp and x0 ----------------
__global__ void k_alpha3(const float* __restrict__ att_s, const float* __restrict__ att_d) {
    int node = (blockIdx.x * blockDim.x + threadIdx.x) >> 5;
    int lane = threadIdx.x & 31;
    if (node >= NN) return;
    float s1[3], s2[3];
#pragma unroll
    for (int l = 0; l < 3; l++) {
        float4 v = *(const float4*)(g_xp + (size_t)node * 384 + l * 128 + lane * 4);
        float4 a = *(const float4*)(att_s + l * 128 + lane * 4);
        float4 b = *(const float4*)(att_d + l * 128 + lane * 4);
        s1[l] = v.x * a.x + v.y * a.y + v.z * a.z + v.w * a.w;
        s2[l] = v.x * b.x + v.y * b.y + v.z * b.z + v.w * b.w;
        st_bf4(g_xpb + (size_t)node * 384 + l * 128 + lane * 4, v);
    }
    float4 vx0 = *(const float4*)(g_x0 + (size_t)node * 128 + lane * 4);
    st_bf4(g_x0b + (size_t)node * 128 + lane * 4, vx0);
#pragma unroll
    for (int off = 16; off; off >>= 1)
#pragma unroll
        for (int l = 0; l < 3; l++) {
            s1[l] += __shfl_down_sync(0xffffffffu, s1[l], off);
            s2[l] += __shfl_down_sync(0xffffffffu, s2[l], off);
        }
    if (lane == 0)
#pragma unroll
        for (int l = 0; l < 3; l++) {
            g_as[l * NN + node] = s1[l];
            g_ad[l * NN + node] = s2[l];
        }
}

// ---------------- fused GAT aggregation (CSR, atomic-free, bf16 gathers) ----------------
__global__ void k_gat_agg(int l, const float* __restrict__ gat_b) {
    int dst = (blockIdx.x * blockDim.x + threadIdx.x) >> 5;
    int lane = threadIdx.x & 31;
    if (dst >= NN) return;
    const int beg = g_off[dst], end = g_off[dst + 1];
    const float ad = g_ad[l * NN + dst];
    const float* asv = g_as + l * NN;
    const __nv_bfloat16* xpB = g_xpb + l * 128 + lane * 4;

    float4 acc = make_float4(0.f, 0.f, 0.f, 0.f);
    float den = 0.f;
#pragma unroll 4
    for (int j = beg; j < end; j++) {
        int src = g_srcl[j];
        float e = asv[src] + ad;
        e = e >= 0.f ? e : NEG_SLOPE * e;
        float w = __expf(e);
        den += w;
        uint2 u = *(const uint2*)(xpB + (size_t)src * 384);
        float2 f0 = __bfloat1622float2(*(__nv_bfloat162*)&u.x);
        float2 f1 = __bfloat1622float2(*(__nv_bfloat162*)&u.y);
        acc.x += w * f0.x; acc.y += w * f0.y; acc.z += w * f1.x; acc.w += w * f1.y;
    }
    float inv = 1.f / (den + 1e-16f);
    float4 b = *(const float4*)(gat_b + l * 128 + lane * 4);
    float4 o;
    o.x = tanhf(acc.x * inv + b.x);
    o.y = tanhf(acc.y * inv + b.y);
    o.z = tanhf(acc.z * inv + b.z);
    o.w = tanhf(acc.w * inv + b.w);
    st_bf4(g_htb + (size_t)dst * 128 + lane * 4, o);
}

// ---------------- LSTM elementwise (float4; FIRST skips c read) ----------------
template <int FIRST>
__global__ void k_lstm() {
    int i = blockIdx.x * blockDim.x + threadIdx.x;
    if (i >= NN * 32) return;
    int n = i >> 5, q = i & 31;
    size_t gb = (size_t)n * GDIM + q * 4;
    float4 ii = *(const float4*)(g_gates + gb);
    float4 ff = *(const float4*)(g_gates + gb + 128);
    float4 gg = *(const float4*)(g_gates + gb + 256);
    float4 oo = *(const float4*)(g_gates + gb + 384);
    size_t idx = (size_t)n * DIM + q * 4;
    float4 x0 = *(const float4*)(g_x0 + idx);
    float4 c, h, x;
    if (FIRST) {
        c.x = sigf(ii.x) * tanhf(gg.x);
        c.y = sigf(ii.y) * tanhf(gg.y);
        c.z = sigf(ii.z) * tanhf(gg.z);
        c.w = sigf(ii.w) * tanhf(gg.w);
    } else {
        c = *(const float4*)(g_c + idx);
        c.x = sigf(ff.x) * c.x + sigf(ii.x) * tanhf(gg.x);
        c.y = sigf(ff.y) * c.y + sigf(ii.y) * tanhf(gg.y);
        c.z = sigf(ff.z) * c.z + sigf(ii.z) * tanhf(gg.z);
        c.w = sigf(ff.w) * c.w + sigf(ii.w) * tanhf(gg.w);
    }
    h.x = sigf(oo.x) * tanhf(c.x);
    h.y = sigf(oo.y) * tanhf(c.y);
    h.z = sigf(oo.z) * tanhf(c.z);
    h.w = sigf(oo.w) * tanhf(c.w);
    x.x = h.x + RESW * x0.x;
    x.y = h.y + RESW * x0.y;
    x.z = h.z + RESW * x0.z;
    x.w = h.w + RESW * x0.w;
    *(float4*)(g_c + idx) = c;
    *(float4*)(g_x + idx) = x;
    st_bf4(g_hb + idx, h);
    st_bf4(g_xb + idx, x);
}

// ---------------- final log_softmax ----------------
__global__ void k_logsoftmax(float* __restrict__ out) {
    int warp = (blockIdx.x * blockDim.x + threadIdx.x) >> 5;
    int lane = threadIdx.x & 31;
    if (warp >= NN) return;
    float* row = out + (size_t)warp * ODIM;
    float v0 = row[lane], v1 = row[lane + 32];
    float m = fmaxf(v0, v1);
#pragma unroll
    for (int off = 16; off; off >>= 1) m = fmaxf(m, __shfl_xor_sync(0xffffffffu, m, off));
    float s = __expf(v0 - m) + __expf(v1 - m);
#pragma unroll
    for (int off = 16; off; off >>= 1) s += __shfl_xor_sync(0xffffffffu, s, off);
    float l = m + logf(s);
    row[lane] = v0 - l;
    row[lane + 32] = v1 - l;
}

// ---------------- launch ----------------
extern "C" void kernel_launch(void* const* d_in, const int* in_sizes, int n_in,
                              void* d_out, int out_size) {
    const float* x_in    = (const float*)d_in[0];
    const int*   eidx    = (const int*)  d_in[1];
    const float* lin1_w  = (const float*)d_in[2];
    const float* lin1_b  = (const float*)d_in[3];
    const float* gat_W   = (const float*)d_in[4];
    const float* att_src = (const float*)d_in[5];
    const float* att_dst = (const float*)d_in[6];
    const float* gat_b   = (const float*)d_in[7];
    const float* lstmWih = (const float*)d_in[8];
    const float* lstmWhh = (const float*)d_in[9];
    const float* lin2_w  = (const float*)d_in[10];
    const float* lin2_b  = (const float*)d_in[11];
    float* out = (float*)d_out;

    float *p_x0, *p_x, *p_xp, *p_gates, *p_Wf, *p_bF;
    __nv_bfloat16 *p_Wlsb, *p_x0b, *p_xb, *p_hb, *p_htb;
    cudaGetSymbolAddress((void**)&p_x0,    g_x0);
    cudaGetSymbolAddress((void**)&p_x,     g_x);
    cudaGetSymbolAddress((void**)&p_xp,    g_xp);
    cudaGetSymbolAddress((void**)&p_gates, g_gates);
    cudaGetSymbolAddress((void**)&p_Wf,    g_Wfused);
    cudaGetSymbolAddress((void**)&p_bF,    g_biasF);
    cudaGetSymbolAddress((void**)&p_Wlsb,  g_Wlsb);
    cudaGetSymbolAddress((void**)&p_x0b,   g_x0b);
    cudaGetSymbolAddress((void**)&p_xb,    g_xb);
    cudaGetSymbolAddress((void**)&p_hb,    g_hb);
    cudaGetSymbolAddress((void**)&p_htb,   g_htb);

    cudaFuncSetAttribute(tgemm<0>, cudaFuncAttributeMaxDynamicSharedMemorySize, TG_SMEM);
    cudaFuncSetAttribute(tgemm<1>, cudaFuncAttributeMaxDynamicSharedMemorySize, TG_SMEM);
    cudaFuncSetAttribute(tgemm_bf16, cudaFuncAttributeMaxDynamicSharedMemorySize, TGB_SMEM);

    // one-time side stream for CSR overlap (created on the uncaptured correctness call)
    static cudaStream_t s2 = nullptr;
    static cudaEvent_t evFork = nullptr, evJoin = nullptr;
    static bool tried = false, use2 = false;
    if (!tried) {
        tried = true;
        use2 = (cudaStreamCreateWithFlags(&s2, cudaStreamNonBlocking) == cudaSuccess) &&
               (cudaEventCreateWithFlags(&evFork, cudaEventDisableTiming) == cudaSuccess) &&
               (cudaEventCreateWithFlags(&evJoin, cudaEventDisableTiming) == cudaSuccess);
    }

    const int T = 256;
    const int rowBlocks = (NN + 127) / 128;   // 782

    // ---- fork: CSR build on s2, projection chain on main stream ----
    cudaStream_t cs = use2 ? s2 : (cudaStream_t)0;
    if (use2) {
        cudaEventRecord(evFork, 0);
        cudaStreamWaitEvent(s2, evFork, 0);
    }
    k_zero_cnt<<<(NN + T - 1) / T, T, 0, cs>>>();
    k_hist<<<(ET + T - 1) / T, T, 0, cs>>>(eidx);
    k_scan1<<<NBLK, SCANB, 0, cs>>>();
    k_scan2<<<1, 32, 0, cs>>>();
    k_scan3<<<NBLK, SCANB, 0, cs>>>();
    k_scatter<<<(ET + T - 1) / T, T, 0, cs>>>(eidx);
    if (use2) cudaEventRecord(evJoin, s2);

    k_prep<<<1200, T>>>(lin1_w, lin1_b, lstmWih, lstmWhh);
    k_compose<<<(384 * 128 + 384 + T - 1) / T, T>>>(lin1_w, lin1_b, gat_W);

    // fused lin1 + all-3-projections (tf32): cols 0-127 -> x0, 128-511 -> xp
    tgemm<1><<<dim3(4, rowBlocks), T, TG_SMEM>>>(x_in, p_Wf, p_bF, p_x0, p_xp, NN, 128, 512, 128);
    k_alpha3<<<(NN * 32 + T - 1) / T, T>>>(att_src, att_dst);

    if (use2) cudaStreamWaitEvent(0, evJoin, 0);   // join before aggregation needs CSR

    for (int l = 0; l < 3; l++) {
        k_gat_agg<<<(NN * 32 + T - 1) / T, T>>>(l, gat_b);
        if (l == 0) {
            // h == 0 exactly -> K=256 over [ht | x0]
            tgemm_bf16<<<dim3(4, rowBlocks), T, TGB_SMEM>>>(p_htb, p_x0b, nullptr,
                                                            p_Wlsb, p_gates,
                                                            NN, 256, GDIM, KLSTM);
            k_lstm<1><<<(NN * 32 + T - 1) / T, T>>>();
        } else {
            tgemm_bf16<<<dim3(4, rowBlocks), T, TGB_SMEM>>>(p_htb, p_xb, p_hb,
                                                            p_Wlsb + (size_t)l * GDIM * KLSTM, p_gates,
                                                            NN, KLSTM, GDIM, KLSTM);
            k_lstm<0><<<(NN * 32 + T - 1) / T, T>>>();
        }
    }

    tgemm<0><<<dim3(1, rowBlocks), T, TG_SMEM>>>(p_x, lin2_w, lin2_b, out, nullptr, NN, 128, ODIM, 128);
    k_logsoftmax<<<(NN * 32 + T - 1) / T, T>>>(out);
}

// round 17
// speedup vs baseline: 1.0218x; 1.0218x over previous
#include <cuda_runtime.h>
#include <cuda_bf16.h>
#include <cstdint>

// ---------------- problem constants ----------------
#define NN     100000
#define EE     1600000
#define ET     1700000          // EE + NN self loops
#define DIM    128
#define ODIM   64
#define GDIM   512              // 4*DIM
#define KLSTM  384              // h_tmp(128) | x(128) | h(128)
#define NEG_SLOPE 0.2f
#define RESW   0.5f
#define SCANB  1024
#define NBLK   ((NN + SCANB - 1) / SCANB)   // 98

// ---------------- device scratch ----------------
__device__ float g_x0[NN * DIM];
__device__ float g_x [NN * DIM];
__device__ float g_c [NN * DIM];
__device__ float g_gates[NN * GDIM];
__device__ float g_as[3 * NN];
__device__ float g_ad[3 * NN];
__device__ int   g_cnt[NN];
__device__ int   g_cur[NN];
__device__ int   g_off[NN + 1];
__device__ int   g_bsum[128];
__device__ int   g_srcl[ET];                // CSR: src ids grouped by dst
__device__ float g_Wfused[512 * DIM];       // rows 0-127: lin1_w; rows 128-511: W1ᵀ·Wg
__device__ float g_biasF[512];
__device__ __nv_bfloat16 g_Wlsb[3 * GDIM * KLSTM];  // gate weights bf16, n-major
__device__ __nv_bfloat16 g_xpb[NN * 3 * DIM];       // bf16 xp (sole copy)
__device__ __nv_bfloat16 g_x0b[NN * DIM];
__device__ __nv_bfloat16 g_xb [NN * DIM];
__device__ __nv_bfloat16 g_hb [NN * DIM];
__device__ __nv_bfloat16 g_htb[NN * DIM];

__device__ __forceinline__ float sigf(float x) { return 1.f / (1.f + __expf(-x)); }

__device__ __forceinline__ void st_bf4(__nv_bfloat16* p, float4 v) {
    __nv_bfloat162* q = (__nv_bfloat162*)p;
    q[0] = __floats2bfloat162_rn(v.x, v.y);
    q[1] = __floats2bfloat162_rn(v.z, v.w);
}

// ---------------- weight prep ----------------
__global__ void k_prep(const float* __restrict__ l1w, const float* __restrict__ l1b,
                       const float* __restrict__ wih, const float* __restrict__ whh) {
    const int W1_TOT = DIM * DIM;
    const int TOT = W1_TOT + 512 + 3 * GDIM * KLSTM;
    for (int i = blockIdx.x * blockDim.x + threadIdx.x; i < TOT; i += gridDim.x * blockDim.x) {
        if (i < W1_TOT) {
            g_Wfused[i] = l1w[i];
        } else if (i < W1_TOT + 512) {
            int n = i - W1_TOT;
            if (n < 128) g_biasF[n] = l1b[n];
        } else {
            int t = i - W1_TOT - 512;
            int l = t / (GDIM * KLSTM);
            int r = t % (GDIM * KLSTM);
            int j = r / KLSTM, k = r % KLSTM;
            float v = (k < 256) ? wih[l * GDIM * 256 + j * 256 + k]
                                : whh[l * GDIM * 128 + j * 128 + (k - 256)];
            g_Wlsb[t] = __float2bfloat16_rn(v);
        }
    }
}

// compose Wc[n][k] = sum_j lin1_w[j][k] * gat_W[l][j][d]; bc[n] = sum_j b1[j]*Wg
__global__ void k_compose(const float* __restrict__ l1w, const float* __restrict__ l1b,
                          const float* __restrict__ gatw) {
    int t = blockIdx.x * blockDim.x + threadIdx.x;
    const int NCMP = 384 * 128;
    if (t < NCMP) {
        int n = t >> 7, k = t & 127;
        int l = n >> 7, d = n & 127;
        const float* wg = gatw + l * 16384 + d;
        float s = 0.f;
#pragma unroll 8
        for (int j = 0; j < 128; j++)
            s += l1w[j * 128 + k] * wg[j * 128];
        g_Wfused[(128 + n) * 128 + k] = s;
    } else if (t < NCMP + 384) {
        int n = t - NCMP;
        int l = n >> 7, d = n & 127;
        const float* wg = gatw + l * 16384 + d;
        float s = 0.f;
#pragma unroll 8
        for (int j = 0; j < 128; j++)
            s += l1b[j] * wg[j * 128];
        g_biasF[128 + n] = s;
    }
}

// ---------------- CSR build (one-time) ----------------
__global__ void k_zero_cnt() {
    for (int i = blockIdx.x * blockDim.x + threadIdx.x; i < NN; i += gridDim.x * blockDim.x) {
        g_cnt[i] = 0; g_cur[i] = 0;
    }
}

__global__ void k_hist(const int* __restrict__ eidx) {
    int e = blockIdx.x * blockDim.x + threadIdx.x;
    if (e >= ET) return;
    int d = (e < EE) ? eidx[EE + e] : e - EE;
    atomicAdd(&g_cnt[d], 1);
}

__global__ void k_scan1() {
    __shared__ int wsum[32];
    int tid = threadIdx.x, lane = tid & 31, wid = tid >> 5;
    int i = blockIdx.x * SCANB + tid;
    int x = (i < NN) ? g_cnt[i] : 0;
#pragma unroll
    for (int off = 1; off < 32; off <<= 1) {
        int t = __shfl_up_sync(0xffffffffu, x, off);
        if (lane >= off) x += t;
    }
    if (lane == 31) wsum[wid] = x;
    __syncthreads();
    if (wid == 0) {
        int y = wsum[lane];
#pragma unroll
        for (int off = 1; off < 32; off <<= 1) {
            int t = __shfl_up_sync(0xffffffffu, y, off);
            if (lane >= off) y += t;
        }
        wsum[lane] = y;
    }
    __syncthreads();
    int incl = x + (wid > 0 ? wsum[wid - 1] : 0);
    if (i < NN) g_off[i + 1] = incl;
    if (tid == SCANB - 1) g_bsum[blockIdx.x] = incl;
}

__global__ void k_scan2() {
    int lane = threadIdx.x;
    int v[4]; int loc = 0;
#pragma unroll
    for (int j = 0; j < 4; j++) {
        int idx = lane * 4 + j;
        v[j] = (idx < NBLK) ? g_bsum[idx] : 0;
        loc += v[j];
    }
    int x = loc;
#pragma unroll
    for (int off = 1; off < 32; off <<= 1) {
        int t = __shfl_up_sync(0xffffffffu, x, off);
        if (lane >= off) x += t;
    }
    int pre = x - loc;
#pragma unroll
    for (int j = 0; j < 4; j++) {
        int idx = lane * 4 + j;
        if (idx < NBLK) g_bsum[idx] = pre;
        pre += v[j];
    }
}

__global__ void k_scan3() {
    int i = blockIdx.x * SCANB + threadIdx.x;
    if (i == 0) g_off[0] = 0;
    if (i < NN) g_off[i + 1] += g_bsum[blockIdx.x];
}

__global__ void k_scatter(const int* __restrict__ eidx) {
    int e = blockIdx.x * blockDim.x + threadIdx.x;
    if (e >= ET) return;
    int s, d;
    if (e < EE) { s = eidx[e]; d = eidx[EE + e]; }
    else        { s = d = e - EE; }
    int pos = g_off[d] + atomicAdd(&g_cur[d], 1);
    g_srcl[pos] = s;
}

// ---------------- common async helpers ----------------
__device__ __forceinline__ void cp16(uint32_t dst, const void* src, int sz) {
    asm volatile("cp.async.cg.shared.global [%0], [%1], 16, %2;\n"
                 :: "r"(dst), "l"(src), "r"(sz));
}

__device__ __forceinline__ void ldm_x4(uint32_t& r0, uint32_t& r1, uint32_t& r2, uint32_t& r3,
                                       uint32_t addr) {
    asm volatile("ldmatrix.sync.aligned.m8n8.x4.shared.b16 {%0,%1,%2,%3}, [%4];"
                 : "=r"(r0), "=r"(r1), "=r"(r2), "=r"(r3) : "r"(addr));
}

// ---------------- tf32 GEMM (projection / lin2), 3-stage, BKT=32 ----------------
// SPLIT=1: block_col<128 -> x0 fp32 (C) + x0b bf16; else -> xpb bf16 only.
#define BKT 32
#define TG_SMEM (6 * 128 * 36 * 4)   // 110592

template <int SPLIT>
__global__ __launch_bounds__(256) void tgemm(
    const float* __restrict__ A0,
    const float* __restrict__ B, const float* __restrict__ bias,
    float* __restrict__ C,
    int M, int K, int Nc, int Bld)
{
    extern __shared__ char smem_raw[];
    float (*sA)[128][36] = (float (*)[128][36])smem_raw;
    float (*sB)[128][36] = (float (*)[128][36])(smem_raw + 3 * 128 * 36 * 4);

    const int tid = threadIdx.x;
    const int wid = tid >> 5, lane = tid & 31;
    const int warpM = wid & 1, warpN = wid >> 1;
    const int block_row = blockIdx.y * 128;
    const int block_col = blockIdx.x * 128;
    const int grp = lane >> 2, tig = lane & 3;

    float acc[4][4][4];
#pragma unroll
    for (int mi = 0; mi < 4; mi++)
#pragma unroll
        for (int ni = 0; ni < 4; ni++)
#pragma unroll
            for (int r = 0; r < 4; r++) acc[mi][ni][r] = 0.f;

    const int nKt = K / BKT;

    auto load_stage = [&](int stage, int kt) {
#pragma unroll
        for (int p = 0; p < 4; p++) {
            int i = tid + p * 256;
            int m = i >> 3, kc = i & 7;
            int gr = block_row + m;
            uint32_t dst = (uint32_t)__cvta_generic_to_shared(&sA[stage][m][kc * 4]);
            cp16(dst, A0 + (size_t)gr * K + kt + kc * 4, gr < M ? 16 : 0);
        }
#pragma unroll
        for (int p = 0; p < 4; p++) {
            int i = tid + p * 256;
            int n = i >> 3, kc = i & 7;
            int gn = block_col + n;
            uint32_t dst = (uint32_t)__cvta_generic_to_shared(&sB[stage][n][kc * 4]);
            cp16(dst, B + (size_t)gn * Bld + kt + kc * 4, gn < Nc ? 16 : 0);
        }
        asm volatile("cp.async.commit_group;\n");
    };

    load_stage(0, 0);
    if (nKt > 1) load_stage(1, BKT);
    else         asm volatile("cp.async.commit_group;\n");

    const int aRow = warpM * 64 + (lane & 15);
    const int aKof = (lane >> 4) << 2;
    const int bRow = warpN * 32 + ((lane >> 4) << 3) + (lane & 7);
    const int bKof = ((lane >> 3) & 1) << 2;

    int s = 0;
    for (int it = 0; it < nKt; it++) {
        asm volatile("cp.async.wait_group 1;\n");
        __syncthreads();
        if (it + 2 < nKt) {
            int ns = s + 2; if (ns >= 3) ns -= 3;
            load_stage(ns, (it + 2) * BKT);
        } else {
            asm volatile("cp.async.commit_group;\n");
        }

        const uint32_t aBase = (uint32_t)__cvta_generic_to_shared(&sA[s][0][0]);
        const uint32_t bBase = (uint32_t)__cvta_generic_to_shared(&sB[s][0][0]);
#pragma unroll
        for (int kk = 0; kk < BKT; kk += 8) {
            uint32_t af[4][4];
#pragma unroll
            for (int mi = 0; mi < 4; mi++) {
                uint32_t addr = aBase + (uint32_t)(((aRow + mi * 16) * 36 + kk + aKof) * 4);
                ldm_x4(af[mi][0], af[mi][1], af[mi][2], af[mi][3], addr);
            }
            uint32_t bf[4][2];
#pragma unroll
            for (int nh = 0; nh < 2; nh++) {
                uint32_t addr = bBase + (uint32_t)(((bRow + nh * 16) * 36 + kk + bKof) * 4);
                uint32_t r0, r1, r2, r3;
                ldm_x4(r0, r1, r2, r3, addr);
                bf[nh * 2][0] = r0; bf[nh * 2][1] = r1;
                bf[nh * 2 + 1][0] = r2; bf[nh * 2 + 1][1] = r3;
            }
#pragma unroll
            for (int mi = 0; mi < 4; mi++)
#pragma unroll
                for (int ni = 0; ni < 4; ni++) {
                    asm volatile(
                        "mma.sync.aligned.m16n8k8.row.col.f32.tf32.tf32.f32 "
                        "{%0,%1,%2,%3}, {%4,%5,%6,%7}, {%8,%9}, {%0,%1,%2,%3};"
                        : "+f"(acc[mi][ni][0]), "+f"(acc[mi][ni][1]),
                          "+f"(acc[mi][ni][2]), "+f"(acc[mi][ni][3])
                        : "r"(af[mi][0]), "r"(af[mi][1]), "r"(af[mi][2]), "r"(af[mi][3]),
                          "r"(bf[ni][0]), "r"(bf[ni][1]));
                }
        }
        if (++s >= 3) s -= 3;
    }

    // ---- epilogue ----
#pragma unroll
    for (int mi = 0; mi < 4; mi++) {
#pragma unroll
        for (int ni = 0; ni < 4; ni++) {
            int gr0 = block_row + warpM * 64 + mi * 16 + grp;
            int lc  = warpN * 32 + ni * 8 + 2 * tig;
            int gcol = block_col + lc;
            if (gcol >= Nc) continue;
            float b0 = 0.f, b1 = 0.f;
            if (bias) { b0 = bias[gcol]; b1 = bias[gcol + 1]; }
            float2 v0 = make_float2(acc[mi][ni][0] + b0, acc[mi][ni][1] + b1);
            float2 v1 = make_float2(acc[mi][ni][2] + b0, acc[mi][ni][3] + b1);
            int gr1 = gr0 + 8;
            if (SPLIT) {
                if (block_col < 128) {
                    if (gr0 < M) {
                        *(float2*)(C + (size_t)gr0 * 128 + gcol) = v0;
                        *(__nv_bfloat162*)(g_x0b + (size_t)gr0 * 128 + gcol) = __floats2bfloat162_rn(v0.x, v0.y);
                    }
                    if (gr1 < M) {
                        *(float2*)(C + (size_t)gr1 * 128 + gcol) = v1;
                        *(__nv_bfloat162*)(g_x0b + (size_t)gr1 * 128 + gcol) = __floats2bfloat162_rn(v1.x, v1.y);
                    }
                } else {
                    int oc = gcol - 128;
                    if (gr0 < M)
                        *(__nv_bfloat162*)(g_xpb + (size_t)gr0 * 384 + oc) = __floats2bfloat162_rn(v0.x, v0.y);
                    if (gr1 < M)
                        *(__nv_bfloat162*)(g_xpb + (size_t)gr1 * 384 + oc) = __floats2bfloat162_rn(v1.x, v1.y);
                }
            } else {
                if (gr0 < M) *(float2*)(C + (size_t)gr0 * Nc + gcol) = v0;
                if (gr1 < M) *(float2*)(C + (size_t)gr1 * Nc + gcol) = v1;
            }
        }
    }
}

// ---------------- bf16 GEMM (gate path), m16n8k16, 3-stage, BKT=32 ----------------
#define TGB_SMEM (6 * 128 * 40 * 2)   // 61440

__global__ __launch_bounds__(256) void tgemm_bf16(
    const __nv_bfloat16* __restrict__ A0, const __nv_bfloat16* __restrict__ A1,
    const __nv_bfloat16* __restrict__ A2,
    const __nv_bfloat16* __restrict__ B, float* __restrict__ C,
    int M, int K, int Nc, int Bld)
{
    extern __shared__ char smem_raw[];
    __nv_bfloat16 (*sA)[128][40] = (__nv_bfloat16 (*)[128][40])smem_raw;
    __nv_bfloat16 (*sB)[128][40] = (__nv_bfloat16 (*)[128][40])(smem_raw + 3 * 128 * 40 * 2);

    const int tid = threadIdx.x;
    const int wid = tid >> 5, lane = tid & 31;
    const int warpM = wid & 1, warpN = wid >> 1;
    const int block_row = blockIdx.y * 128;
    const int block_col = blockIdx.x * 128;
    const int grp = lane >> 2, tig = lane & 3;

    float acc[4][4][4];
#pragma unroll
    for (int mi = 0; mi < 4; mi++)
#pragma unroll
        for (int ni = 0; ni < 4; ni++)
#pragma unroll
            for (int r = 0; r < 4; r++) acc[mi][ni][r] = 0.f;

    const int nKt = K / BKT;

    auto load_stage = [&](int stage, int kt) {
        int seg = kt >> 7;
        const __nv_bfloat16* Ap = (seg == 0) ? A0 : (seg == 1) ? A1 : A2;
        int kb = kt & 127;
#pragma unroll
        for (int p = 0; p < 2; p++) {
            int i = tid + p * 256;
            int m = i >> 2, kc = i & 3;
            int gr = block_row + m;
            uint32_t dst = (uint32_t)__cvta_generic_to_shared(&sA[stage][m][kc * 8]);
            cp16(dst, Ap + (size_t)gr * 128 + kb + kc * 8, gr < M ? 16 : 0);
        }
#pragma unroll
        for (int p = 0; p < 2; p++) {
            int i = tid + p * 256;
            int n = i >> 2, kc = i & 3;
            int gn = block_col + n;
            uint32_t dst = (uint32_t)__cvta_generic_to_shared(&sB[stage][n][kc * 8]);
            cp16(dst, B + (size_t)gn * Bld + kt + kc * 8, gn < Nc ? 16 : 0);
        }
        asm volatile("cp.async.commit_group;\n");
    };

    load_stage(0, 0);
    load_stage(1, BKT);

    const int aRow = warpM * 64 + (lane & 15);
    const int aK8  = (lane >> 4) << 3;
    const int bRow = warpN * 32 + ((lane >> 3) & 1) * 8 + (lane & 7);
    const int bK8  = (lane >> 4) << 3;

    int s = 0;
    for (int it = 0; it < nKt; it++) {
        asm volatile("cp.async.wait_group 1;\n");
        __syncthreads();
        if (it + 2 < nKt) {
            int ns = s + 2; if (ns >= 3) ns -= 3;
            load_stage(ns, (it + 2) * BKT);
        } else {
            asm volatile("cp.async.commit_group;\n");
        }

        const uint32_t aBase = (uint32_t)__cvta_generic_to_shared(&sA[s][0][0]);
        const uint32_t bBase = (uint32_t)__cvta_generic_to_shared(&sB[s][0][0]);
#pragma unroll
        for (int kk = 0; kk < BKT; kk += 16) {
            uint32_t af[4][4];
#pragma unroll
            for (int mi = 0; mi < 4; mi++) {
                uint32_t addr = aBase + (uint32_t)(((aRow + mi * 16) * 40 + kk + aK8) * 2);
                ldm_x4(af[mi][0], af[mi][1], af[mi][2], af[mi][3], addr);
            }
            uint32_t bf[4][2];
#pragma unroll
            for (int nh = 0; nh < 2; nh++) {
                uint32_t addr = bBase + (uint32_t)(((bRow + nh * 16) * 40 + kk + bK8) * 2);
                uint32_t r0, r1, r2, r3;
                ldm_x4(r0, r1, r2, r3, addr);
                bf[nh * 2][0] = r0; bf[nh * 2][1] = r2;
                bf[nh * 2 + 1][0] = r1; bf[nh * 2 + 1][1] = r3;
            }
#pragma unroll
            for (int mi = 0; mi < 4; mi++)
#pragma unroll
                for (int ni = 0; ni < 4; ni++) {
                    asm volatile(
                        "mma.sync.aligned.m16n8k16.row.col.f32.bf16.bf16.f32 "
                        "{%0,%1,%2,%3}, {%4,%5,%6,%7}, {%8,%9}, {%0,%1,%2,%3};"
                        : "+f"(acc[mi][ni][0]), "+f"(acc[mi][ni][1]),
                          "+f"(acc[mi][ni][2]), "+f"(acc[mi][ni][3])
                        : "r"(af[mi][0]), "r"(af[mi][1]), "r"(af[mi][2]), "r"(af[mi][3]),
                          "r"(bf[ni][0]), "r"(bf[ni][1]));
                }
        }
        if (++s >= 3) s -= 3;
    }

#pragma unroll
    for (int mi = 0; mi < 4; mi++) {
#pragma unroll
        for (int ni = 0; ni < 4; ni++) {
            int gr0 = block_row + warpM * 64 + mi * 16 + grp;
            int gc  = block_col + warpN * 32 + ni * 8 + 2 * tig;
            if (gc >= Nc) continue;
            if (gr0 < M) {
                float2 v = make_float2(acc[mi][ni][0], acc[mi][ni][1]);
                *(float2*)(C + (size_t)gr0 * Nc + gc) = v;
            }
            int gr1 = gr0 + 8;
            if (gr1 < M) {
                float2 v = make_float2(acc[mi][ni][2], acc[mi][ni][3]);
                *(float2*)(C + (size_t)gr1 * Nc + gc) = v;
            }
        }
    }
}

// ---------------- attention coefficients from bf16 xpb ----------------
__global__ void k_alpha3(const float* __restrict__ att_s, const float* __restrict__ att_d) {
    int node = (blockIdx.x * blockDim.x + threadIdx.x) >> 5;
    int lane = threadIdx.x & 31;
    if (node >= NN) return;
    float s1[3], s2[3];
#pragma unroll
    for (int l = 0; l < 3; l++) {
        uint2 u = *(const uint2*)(g_xpb + (size_t)node * 384 + l * 128 + lane * 4);
        float2 f0 = __bfloat1622float2(*(__nv_bfloat162*)&u.x);
        float2 f1 = __bfloat1622float2(*(__nv_bfloat162*)&u.y);
        float4 a = *(const float4*)(att_s + l * 128 + lane * 4);
        float4 b = *(const float4*)(att_d + l * 128 + lane * 4);
        s1[l] = f0.x * a.x + f0.y * a.y + f1.x * a.z + f1.y * a.w;
        s2[l] = f0.x * b.x + f0.y * b.y + f1.x * b.z + f1.y * b.w;
    }
#pragma unroll
    for (int off = 16; off; off >>= 1)
#pragma unroll
        for (int l = 0; l < 3; l++) {
            s1[l] += __shfl_down_sync(0xffffffffu, s1[l], off);
            s2[l] += __shfl_down_sync(0xffffffffu, s2[l], off);
        }
    if (lane == 0)
#pragma unroll
        for (int l = 0; l < 3; l++) {
            g_as[l * NN + node] = s1[l];
            g_ad[l * NN + node] = s2[l];
        }
}

// ---------------- fused GAT aggregation (CSR, atomic-free, bf16 gathers) ----------------
__global__ void k_gat_agg(int l, const float* __restrict__ gat_b) {
    int dst = (blockIdx.x * blockDim.x + threadIdx.x) >> 5;
    int lane = threadIdx.x & 31;
    if (dst >= NN) return;
    const int beg = g_off[dst], end = g_off[dst + 1];
    const float ad = g_ad[l * NN + dst];
    const float* asv = g_as + l * NN;
    const __nv_bfloat16* xpB = g_xpb + l * 128 + lane * 4;

    float4 acc = make_float4(0.f, 0.f, 0.f, 0.f);
    float den = 0.f;
#pragma unroll 4
    for (int j = beg; j < end; j++) {
        int src = g_srcl[j];
        float e = asv[src] + ad;
        e = e >= 0.f ? e : NEG_SLOPE * e;
        float w = __expf(e);
        den += w;
        uint2 u = *(const uint2*)(xpB + (size_t)src * 384);
        float2 f0 = __bfloat1622float2(*(__nv_bfloat162*)&u.x);
        float2 f1 = __bfloat1622float2(*(__nv_bfloat162*)&u.y);
        acc.x += w * f0.x; acc.y += w * f0.y; acc.z += w * f1.x; acc.w += w * f1.y;
    }
    float inv = 1.f / (den + 1e-16f);
    float4 b = *(const float4*)(gat_b + l * 128 + lane * 4);
    float4 o;
    o.x = tanhf(acc.x * inv + b.x);
    o.y = tanhf(acc.y * inv + b.y);
    o.z = tanhf(acc.z * inv + b.z);
    o.w = tanhf(acc.w * inv + b.w);
    st_bf4(g_htb + (size_t)dst * 128 + lane * 4, o);
}

// ---------------- LSTM elementwise (float4; FIRST skips c read) ----------------
template <int FIRST>
__global__ void k_lstm() {
    int i = blockIdx.x * blockDim.x + threadIdx.x;
    if (i >= NN * 32) return;
    int n = i >> 5, q = i & 31;
    size_t gb = (size_t)n * GDIM + q * 4;
    float4 ii = *(const float4*)(g_gates + gb);
    float4 ff = *(const float4*)(g_gates + gb + 128);
    float4 gg = *(const float4*)(g_gates + gb + 256);
    float4 oo = *(const float4*)(g_gates + gb + 384);
    size_t idx = (size_t)n * DIM + q * 4;
    float4 x0 = *(const float4*)(g_x0 + idx);
    float4 c, h, x;
    if (FIRST) {
        c.x = sigf(ii.x) * tanhf(gg.x);
        c.y = sigf(ii.y) * tanhf(gg.y);
        c.z = sigf(ii.z) * tanhf(gg.z);
        c.w = sigf(ii.w) * tanhf(gg.w);
    } else {
        c = *(const float4*)(g_c + idx);
        c.x = sigf(ff.x) * c.x + sigf(ii.x) * tanhf(gg.x);
        c.y = sigf(ff.y) * c.y + sigf(ii.y) * tanhf(gg.y);
        c.z = sigf(ff.z) * c.z + sigf(ii.z) * tanhf(gg.z);
        c.w = sigf(ff.w) * c.w + sigf(ii.w) * tanhf(gg.w);
    }
    h.x = sigf(oo.x) * tanhf(c.x);
    h.y = sigf(oo.y) * tanhf(c.y);
    h.z = sigf(oo.z) * tanhf(c.z);
    h.w = sigf(oo.w) * tanhf(c.w);
    x.x = h.x + RESW * x0.x;
    x.y = h.y + RESW * x0.y;
    x.z = h.z + RESW * x0.z;
    x.w = h.w + RESW * x0.w;
    *(float4*)(g_c + idx) = c;
    *(float4*)(g_x + idx) = x;
    st_bf4(g_hb + idx, h);
    st_bf4(g_xb + idx, x);
}

// ---------------- final log_softmax ----------------
__global__ void k_logsoftmax(float* __restrict__ out) {
    int warp = (blockIdx.x * blockDim.x + threadIdx.x) >> 5;
    int lane = threadIdx.x & 31;
    if (warp >= NN) return;
    float* row = out + (size_t)warp * ODIM;
    float v0 = row[lane], v1 = row[lane + 32];
    float m = fmaxf(v0, v1);
#pragma unroll
    for (int off = 16; off; off >>= 1) m = fmaxf(m, __shfl_xor_sync(0xffffffffu, m, off));
    float s = __expf(v0 - m) + __expf(v1 - m);
#pragma unroll
    for (int off = 16; off; off >>= 1) s += __shfl_xor_sync(0xffffffffu, s, off);
    float l = m + logf(s);
    row[lane] = v0 - l;
    row[lane + 32] = v1 - l;
}

// ---------------- launch ----------------
extern "C" void kernel_launch(void* const* d_in, const int* in_sizes, int n_in,
                              void* d_out, int out_size) {
    const float* x_in    = (const float*)d_in[0];
    const int*   eidx    = (const int*)  d_in[1];
    const float* lin1_w  = (const float*)d_in[2];
    const float* lin1_b  = (const float*)d_in[3];
    const float* gat_W   = (const float*)d_in[4];
    const float* att_src = (const float*)d_in[5];
    const float* att_dst = (const float*)d_in[6];
    const float* gat_b   = (const float*)d_in[7];
    const float* lstmWih = (const float*)d_in[8];
    const float* lstmWhh = (const float*)d_in[9];
    const float* lin2_w  = (const float*)d_in[10];
    const float* lin2_b  = (const float*)d_in[11];
    float* out = (float*)d_out;

    float *p_x0, *p_x, *p_gates, *p_Wf, *p_bF;
    __nv_bfloat16 *p_Wlsb, *p_x0b, *p_xb, *p_hb, *p_htb;
    cudaGetSymbolAddress((void**)&p_x0,    g_x0);
    cudaGetSymbolAddress((void**)&p_x,     g_x);
    cudaGetSymbolAddress((void**)&p_gates, g_gates);
    cudaGetSymbolAddress((void**)&p_Wf,    g_Wfused);
    cudaGetSymbolAddress((void**)&p_bF,    g_biasF);
    cudaGetSymbolAddress((void**)&p_Wlsb,  g_Wlsb);
    cudaGetSymbolAddress((void**)&p_x0b,   g_x0b);
    cudaGetSymbolAddress((void**)&p_xb,    g_xb);
    cudaGetSymbolAddress((void**)&p_hb,    g_hb);
    cudaGetSymbolAddress((void**)&p_htb,   g_htb);

    cudaFuncSetAttribute(tgemm<0>, cudaFuncAttributeMaxDynamicSharedMemorySize, TG_SMEM);
    cudaFuncSetAttribute(tgemm<1>, cudaFuncAttributeMaxDynamicSharedMemorySize, TG_SMEM);
    cudaFuncSetAttribute(tgemm_bf16, cudaFuncAttributeMaxDynamicSharedMemorySize, TGB_SMEM);

    // one-time side stream for CSR overlap
    static cudaStream_t s2 = nullptr;
    static cudaEvent_t evFork = nullptr, evJoin = nullptr;
    static bool tried = false, use2 = false;
    if (!tried) {
        tried = true;
        use2 = (cudaStreamCreateWithFlags(&s2, cudaStreamNonBlocking) == cudaSuccess) &&
               (cudaEventCreateWithFlags(&evFork, cudaEventDisableTiming) == cudaSuccess) &&
               (cudaEventCreateWithFlags(&evJoin, cudaEventDisableTiming) == cudaSuccess);
    }

    const int T = 256;
    const int rowBlocks = (NN + 127) / 128;   // 782

    // ---- fork: CSR build on s2, projection chain on main stream ----
    cudaStream_t cs = use2 ? s2 : (cudaStream_t)0;
    if (use2) {
        cudaEventRecord(evFork, 0);
        cudaStreamWaitEvent(s2, evFork, 0);
    }
    k_zero_cnt<<<(NN + T - 1) / T, T, 0, cs>>>();
    k_hist<<<(ET + T - 1) / T, T, 0, cs>>>(eidx);
    k_scan1<<<NBLK, SCANB, 0, cs>>>();
    k_scan2<<<1, 32, 0, cs>>>();
    k_scan3<<<NBLK, SCANB, 0, cs>>>();
    k_scatter<<<(ET + T - 1) / T, T, 0, cs>>>(eidx);
    if (use2) cudaEventRecord(evJoin, s2);

    k_prep<<<1200, T>>>(lin1_w, lin1_b, lstmWih, lstmWhh);
    k_compose<<<(384 * 128 + 384 + T - 1) / T, T>>>(lin1_w, lin1_b, gat_W);

    // fused lin1 + all-3-projections: cols 0-127 -> x0 fp32 + x0b bf16; 128-511 -> xpb bf16
    tgemm<1><<<dim3(4, rowBlocks), T, TG_SMEM>>>(x_in, p_Wf, p_bF, p_x0, NN, 128, 512, 128);
    k_alpha3<<<(NN * 32 + T - 1) / T, T>>>(att_src, att_dst);

    if (use2) cudaStreamWaitEvent(0, evJoin, 0);   // join before aggregation needs CSR

    for (int l = 0; l < 3; l++) {
        k_gat_agg<<<(NN * 32 + T - 1) / T, T>>>(l, gat_b);
        if (l == 0) {
            tgemm_bf16<<<dim3(4, rowBlocks), T, TGB_SMEM>>>(p_htb, p_x0b, nullptr,
                                                            p_Wlsb, p_gates,
                                                            NN, 256, GDIM, KLSTM);
            k_lstm<1><<<(NN * 32 + T - 1) / T, T>>>();
        } else {
            tgemm_bf16<<<dim3(4, rowBlocks), T, TGB_SMEM>>>(p_htb, p_xb, p_hb,
                                                            p_Wlsb + (size_t)l * GDIM * KLSTM, p_gates,
                                                            NN, KLSTM, GDIM, KLSTM);
            k_lstm<0><<<(NN * 32 + T - 1) / T, T>>>();
        }
    }

    tgemm<0><<<dim3(1, rowBlocks), T, TG_SMEM>>>(p_x, lin2_w, lin2_b, out, NN, 128, ODIM, 128);
    k_logsoftmax<<<(NN * 32 + T - 1) / T, T>>>(out);
}